// round 5
// baseline (speedup 1.0000x reference)
#include <cuda_runtime.h>
#include <cstdint>
#include <math.h>

// Problem dims (fixed)
#define B_      2
#define L_      2048
#define D_      2048
#define M_      4096          // B*L
#define H_      16
#define DK      64
#define DV      128
#define NQK     1024          // H*DK
#define CHUNK   64
#define NCHUNK  32            // L / CHUNK
#define SCALE_QK 0.08838834764831845f   // 128^-0.5
#define INV_NORM 0.0625f                 // 1/16
#define LN_EPS   1e-5f

// ---------------- scratch (static device globals; no allocation) -------------
__device__ float g_q   [(size_t)M_ * NQK];
__device__ float g_k   [(size_t)M_ * NQK];
__device__ float g_gate[(size_t)M_ * NQK];
__device__ float g_kg1 [(size_t)M_ * 16];
__device__ float g_v   [(size_t)M_ * D_];
__device__ float g_gp  [(size_t)M_ * D_];
__device__ float g_y   [(size_t)M_ * D_];
__device__ float g_S   [(size_t)B_ * H_ * NCHUNK * DK * DV];

// ======================= PTX helpers (non-'a' features only) ==================
__device__ __forceinline__ uint32_t smem_u32(const void* p) {
    uint32_t a;
    asm("{ .reg .u64 t; cvta.to.shared.u64 t, %1; cvt.u32.u64 %0, t; }" : "=r"(a) : "l"(p));
    return a;
}
__device__ __forceinline__ void cp_async16(uint32_t dst, const void* src) {
    asm volatile("cp.async.cg.shared.global [%0], [%1], 16;" :: "r"(dst), "l"(src) : "memory");
}
#define CP_COMMIT() asm volatile("cp.async.commit_group;" ::: "memory")
#define CP_WAIT(N)  asm volatile("cp.async.wait_group %0;" :: "n"(N) : "memory")

__device__ __forceinline__ uint32_t f2tf(float f) {
    uint32_t u;
    asm("cvt.rna.tf32.f32 %0, %1;" : "=r"(u) : "f"(f));
    return u;
}
__device__ __forceinline__ void mma_tf32(float c[4], const uint32_t a[4], const uint32_t b[2]) {
    asm volatile(
        "mma.sync.aligned.m16n8k8.row.col.f32.tf32.tf32.f32 "
        "{%0,%1,%2,%3}, {%4,%5,%6,%7}, {%8,%9}, {%0,%1,%2,%3};"
        : "+f"(c[0]), "+f"(c[1]), "+f"(c[2]), "+f"(c[3])
        : "r"(a[0]), "r"(a[1]), "r"(a[2]), "r"(a[3]), "r"(b[0]), "r"(b[1]));
}

// ======================= tf32 GEMM (mma.sync), multi-target ===================
// A [M,K] row-major fp32. Up to 4 weight matrices [.,K] row-major selected by
// blockIdx.x tile-column routing. C = alpha * A @ W^T (+ bias).
// NOTE: W row index is tile-local (wrow = (c-start)*BN); callers must pre-offset
// the W pointer when routing multiple column-ranges of the SAME weight matrix.
// Tile 128x128x32, 8 warps (2x4), warp tile 64x32. cp.async double-buffered.
#define BM 128
#define BN 128
#define BK 32
#define PITCH 36                         // floats per smem row (pad for banks)
#define TSTRIDE (128*PITCH)              // floats per tile stage
#define GEMM_SMEM_BYTES (4*TSTRIDE*4)    // A[2] + B[2]

__global__ __launch_bounds__(256, 2)
void tf32_gemm_multi(
    const float* __restrict__ A,
    const float* __restrict__ W0, const float* __restrict__ W1,
    const float* __restrict__ W2, const float* __restrict__ W3,
    const float* __restrict__ bias3,
    float* __restrict__ C0, float* __restrict__ C1,
    float* __restrict__ C2, float* __restrict__ C3,
    int K,
    int s1, int s2, int s3,
    int cb1, int cb2, int cb3,
    int N0, int N1, int N2, int N3,
    float a0, float a1, float a2, float a3)
{
    extern __shared__ float smf[];
    float* Asm = smf;
    float* Bsm = smf + 2*TSTRIDE;
    const uint32_t Abase_s = smem_u32(Asm);
    const uint32_t Bbase_s = smem_u32(Bsm);

    const int c = blockIdx.x;
    const int sel = (c >= s3) ? 3 : (c >= s2) ? 2 : (c >= s1) ? 1 : 0;
    const float* W = (sel == 0) ? W0 : (sel == 1) ? W1 : (sel == 2) ? W2 : W3;
    float*       C = (sel == 0) ? C0 : (sel == 1) ? C1 : (sel == 2) ? C2 : C3;
    const int start   = (sel == 0) ? 0 : (sel == 1) ? s1 : (sel == 2) ? s2 : s3;
    const int colbase = (sel == 0) ? 0 : (sel == 1) ? cb1 : (sel == 2) ? cb2 : cb3;
    const int N       = (sel == 0) ? N0 : (sel == 1) ? N1 : (sel == 2) ? N2 : N3;
    const float alpha = (sel == 0) ? a0 : (sel == 1) ? a1 : (sel == 2) ? a2 : a3;
    const float* bias = (sel == 3) ? bias3 : nullptr;

    const int tid = threadIdx.x;
    const int wid = tid >> 5;
    const int lane = tid & 31;
    const int g  = lane >> 2;        // 0..7
    const int t4 = lane & 3;         // 0..3
    const int wm = wid >> 2;         // 0..1 -> 64-row block
    const int wn = wid & 3;          // 0..3 -> 32-col block
    const int m0 = blockIdx.y * BM;
    const int wrow = (c - start) * BN;        // tile-local row offset inside W
    const int n0g = wrow + colbase;           // global output column base

    const float* Ag = A + (size_t)m0   * K;
    const float* Bg = W + (size_t)wrow * K;

    float cacc[4][4][4];
#pragma unroll
    for (int i = 0; i < 4; ++i)
#pragma unroll
        for (int j = 0; j < 4; ++j)
#pragma unroll
            for (int e = 0; e < 4; ++e) cacc[i][j][e] = 0.f;

    const int niter = K / BK;

    auto load_tile = [&](int kt, int s) {
        const int k0 = kt * BK;
        const uint32_t sa = Abase_s + (uint32_t)s * TSTRIDE * 4;
        const uint32_t sb = Bbase_s + (uint32_t)s * TSTRIDE * 4;
#pragma unroll
        for (int i = 0; i < 4; ++i) {
            int idx = tid + 256*i;
            int r = idx >> 3, sg = idx & 7;
            cp_async16(sa + (uint32_t)(r*PITCH + sg*4)*4, Ag + (size_t)r*K + k0 + sg*4);
        }
#pragma unroll
        for (int i = 0; i < 4; ++i) {
            int idx = tid + 256*i;
            int r = idx >> 3, sg = idx & 7;
            cp_async16(sb + (uint32_t)(r*PITCH + sg*4)*4, Bg + (size_t)r*K + k0 + sg*4);
        }
    };

    load_tile(0, 0);
    CP_COMMIT();

    for (int kt = 0; kt < niter; ++kt) {
        const int s = kt & 1;
        if (kt + 1 < niter) {
            load_tile(kt + 1, s ^ 1);
            CP_COMMIT();
            CP_WAIT(1);
        } else {
            CP_WAIT(0);
        }
        __syncthreads();

        const float* As = Asm + s * TSTRIDE;
        const float* Bs = Bsm + s * TSTRIDE;
#pragma unroll
        for (int kk = 0; kk < 4; ++kk) {
            uint32_t af[4][4];
#pragma unroll
            for (int mt = 0; mt < 4; ++mt) {
                const int r0 = wm*64 + mt*16 + g;
                const float* pa = As + kk*8 + t4;
                af[mt][0] = f2tf(pa[(r0    )*PITCH    ]);
                af[mt][1] = f2tf(pa[(r0 + 8)*PITCH    ]);
                af[mt][2] = f2tf(pa[(r0    )*PITCH + 4]);
                af[mt][3] = f2tf(pa[(r0 + 8)*PITCH + 4]);
            }
            uint32_t bf[4][2];
#pragma unroll
            for (int nt = 0; nt < 4; ++nt) {
                const int nr = wn*32 + nt*8 + g;
                const float* pb = Bs + (size_t)nr*PITCH + kk*8 + t4;
                bf[nt][0] = f2tf(pb[0]);
                bf[nt][1] = f2tf(pb[4]);
            }
#pragma unroll
            for (int mt = 0; mt < 4; ++mt)
#pragma unroll
                for (int nt = 0; nt < 4; ++nt)
                    mma_tf32(cacc[mt][nt], af[mt], bf[nt]);
        }
        __syncthreads();
    }

    // epilogue
#pragma unroll
    for (int mt = 0; mt < 4; ++mt) {
#pragma unroll
        for (int nt = 0; nt < 4; ++nt) {
            const int col = n0g + wn*32 + nt*8 + 2*t4;
            float b0 = bias ? __ldg(bias + col)     : 0.f;
            float b1 = bias ? __ldg(bias + col + 1) : 0.f;
            const int r0 = m0 + wm*64 + mt*16 + g;
            float2 v0 = make_float2(cacc[mt][nt][0]*alpha + b0, cacc[mt][nt][1]*alpha + b1);
            float2 v1 = make_float2(cacc[mt][nt][2]*alpha + b0, cacc[mt][nt][3]*alpha + b1);
            *(float2*)(C + (size_t)r0      * N + col) = v0;
            *(float2*)(C + (size_t)(r0+8)  * N + col) = v1;
        }
    }
}

// ---------------- kg1 = x @ Wkg1^T  ------------------------------------------
__global__ __launch_bounds__(256) void kg1_kernel(
    const float* __restrict__ x, const float* __restrict__ Wkg1,
    float* __restrict__ out)
{
    __shared__ float xs[16][68];
    __shared__ float ws[16][68];
    const int tid = threadIdx.x;
    const int tx = tid & 15;
    const int ty = tid >> 4;
    const int m0 = blockIdx.x * 16;
    const int lrow = tid >> 4;
    const int lcol = (tid & 15) * 4;
    float acc = 0.f;
    for (int kt = 0; kt < D_; kt += 64) {
        float4 xv = *(const float4*)(x    + (size_t)(m0 + lrow)*D_ + kt + lcol);
        float4 wv = *(const float4*)(Wkg1 + (size_t)lrow*D_        + kt + lcol);
        *(float4*)&xs[lrow][lcol] = xv;
        *(float4*)&ws[lrow][lcol] = wv;
        __syncthreads();
#pragma unroll
        for (int kk = 0; kk < 64; ++kk)
            acc = fmaf(xs[ty][kk], ws[tx][kk], acc);
        __syncthreads();
    }
    out[(size_t)(m0 + ty)*16 + tx] = acc;
}

// ---------------- gate = log_sigmoid(kg1 @ Wkg2^T + bkg2) / 16 ---------------
__global__ __launch_bounds__(256) void gate_kernel(
    const float* __restrict__ Wkg2, const float* __restrict__ bkg2)
{
    __shared__ float row[16];
    const int tid = threadIdx.x;
    const int m = blockIdx.x;
    if (tid < 16) row[tid] = g_kg1[(size_t)m*16 + tid];
    __syncthreads();
#pragma unroll
    for (int i = 0; i < 4; ++i) {
        int n = i*256 + tid;
        const float4* wp = (const float4*)(Wkg2 + (size_t)n*16);
        float4 w0 = wp[0], w1 = wp[1], w2 = wp[2], w3 = wp[3];
        float acc = bkg2[n];
        acc += row[0]*w0.x + row[1]*w0.y + row[2]*w0.z + row[3]*w0.w;
        acc += row[4]*w1.x + row[5]*w1.y + row[6]*w1.z + row[7]*w1.w;
        acc += row[8]*w2.x + row[9]*w2.y + row[10]*w2.z + row[11]*w2.w;
        acc += row[12]*w3.x + row[13]*w3.y + row[14]*w3.z + row[15]*w3.w;
        float z = acc;
        // log_sigmoid(z) = min(z,0) - log1p(exp(-|z|)); fast-math MUFU version
        float e  = __expf(-fabsf(z));
        float ls = fminf(z, 0.f) - __logf(1.f + e);
        g_gate[(size_t)m*NQK + n] = ls * INV_NORM;
    }
}

// ---------------- pass 1: chunk states, parallel over dv quarters ------------
__global__ __launch_bounds__(128) void state_kernel()
{
    __shared__ float Gs[64][65];
    __shared__ float kb[64][68];
    __shared__ float vs[64][40];
    const int bq = blockIdx.x;         // dv quarter
    const int bh = blockIdx.y;
    const int b = bh >> 4, h = bh & 15;
    const int tid = threadIdx.x;
    const int ty = tid >> 3;           // 0..15 (dk block of 4)
    const int tx = tid & 7;            // 0..7  (dv block of 4 within 32)
    const int mb = b * L_;

    float S[4][4];
#pragma unroll
    for (int dd = 0; dd < 4; ++dd)
#pragma unroll
        for (int jj = 0; jj < 4; ++jj) S[dd][jj] = 0.f;

    for (int c = 0; c < NCHUNK; ++c) {
        const int m0 = mb + c * CHUNK;
        float* sp = g_S + (size_t)(bh * NCHUNK + c) * (DK * DV) + (size_t)bq * 32;
#pragma unroll
        for (int dd = 0; dd < 4; ++dd)
            *(float4*)(sp + (size_t)(ty*4 + dd)*DV + tx*4) =
                make_float4(S[dd][0], S[dd][1], S[dd][2], S[dd][3]);

        if (tid < 64) {
            float run = 0.f;
            for (int t = 0; t < CHUNK; ++t) {
                run += g_gate[(size_t)(m0 + t)*NQK + h*DK + tid];
                Gs[t][tid] = run;
            }
        }
        __syncthreads();
        for (int e = tid; e < CHUNK*DK; e += 128) {
            int t = e >> 6, d = e & 63;
            kb[t][d] = g_k[(size_t)(m0 + t)*NQK + h*DK + d] * __expf(Gs[63][d] - Gs[t][d]);
        }
        for (int e = tid; e < CHUNK*32; e += 128) {
            int t = e >> 5, j = e & 31;
            vs[t][j] = g_v[(size_t)(m0 + t)*D_ + h*DV + bq*32 + j];
        }
        __syncthreads();
        float E[4];
#pragma unroll
        for (int dd = 0; dd < 4; ++dd) E[dd] = __expf(Gs[63][ty*4 + dd]);
#pragma unroll
        for (int dd = 0; dd < 4; ++dd)
#pragma unroll
            for (int jj = 0; jj < 4; ++jj) S[dd][jj] *= E[dd];
        for (int t = 0; t < CHUNK; ++t) {
            float4 kv = *(const float4*)&kb[t][ty*4];
            float4 vv = *(const float4*)&vs[t][tx*4];
            float ka[4] = {kv.x, kv.y, kv.z, kv.w};
            float va[4] = {vv.x, vv.y, vv.z, vv.w};
#pragma unroll
            for (int dd = 0; dd < 4; ++dd)
#pragma unroll
                for (int jj = 0; jj < 4; ++jj)
                    S[dd][jj] = fmaf(ka[dd], va[jj], S[dd][jj]);
        }
        __syncthreads();
    }
}

// ---------------- pass 2: chunk outputs + LN + SiLU gating --------------------
__global__ __launch_bounds__(256) void output_kernel()
{
    extern __shared__ float sm[];
    float (*qs)[68]  = (float(*)[68]) sm;
    float (*ks)[68]  = (float(*)[68])(sm + 64*68);
    float (*GA)[65]  = (float(*)[65])(sm + 2*64*68);
    float (*vs)[132] = (float(*)[132])(sm + 2*64*68 + 64*65);
    float (*Sp)[132] = (float(*)[132])(sm + 2*64*68 + 64*65 + 64*132);

    const int c  = blockIdx.x;
    const int bh = blockIdx.y;
    const int b = bh >> 4, h = bh & 15;
    const int tid = threadIdx.x;
    const int m0 = b * L_ + c * CHUNK;
    const size_t sbase = (size_t)(bh * NCHUNK + c) * (DK * DV);

    if (tid < 64) {
        float run = 0.f;
        for (int t = 0; t < CHUNK; ++t) {
            run += g_gate[(size_t)(m0 + t)*NQK + h*DK + tid];
            GA[t][tid] = run;
        }
    }
    __syncthreads();
    for (int e = tid; e < CHUNK*DK; e += 256) {
        int t = e >> 6, d = e & 63;
        float G = GA[t][d];
        size_t gi = (size_t)(m0 + t)*NQK + h*DK + d;
        qs[t][d] = g_q[gi] * __expf(G);
        ks[t][d] = g_k[gi] * __expf(-G);
    }
    for (int e = tid; e < CHUNK*DV; e += 256) {
        int t = e >> 7, j = e & 127;
        vs[t][j] = g_v[(size_t)(m0 + t)*D_ + h*DV + j];
        Sp[t][j] = g_S[sbase + e];
    }
    __syncthreads();
    for (int e = tid; e < CHUNK*CHUNK; e += 256) {
        int t = e >> 6, s = e & 63;
        float acc = 0.f;
        if (s <= t) {
            const float4* qp = (const float4*)&qs[t][0];
            const float4* kp = (const float4*)&ks[s][0];
#pragma unroll
            for (int d4 = 0; d4 < 16; ++d4) {
                float4 qa = qp[d4], kk4 = kp[d4];
                acc = fmaf(qa.x, kk4.x, acc);
                acc = fmaf(qa.y, kk4.y, acc);
                acc = fmaf(qa.z, kk4.z, acc);
                acc = fmaf(qa.w, kk4.w, acc);
            }
        }
        GA[t][s] = acc;
    }
    __syncthreads();
    const int t  = tid >> 2;
    const int qq = tid & 3;
    float o[32];
#pragma unroll
    for (int jj = 0; jj < 32; ++jj) o[jj] = 0.f;

    for (int d = 0; d < DK; ++d) {
        float qv = qs[t][d];
        const float4* sp4 = (const float4*)&Sp[d][qq*32];
#pragma unroll
        for (int j4 = 0; j4 < 8; ++j4) {
            float4 vv = sp4[j4];
            o[j4*4+0] = fmaf(qv, vv.x, o[j4*4+0]);
            o[j4*4+1] = fmaf(qv, vv.y, o[j4*4+1]);
            o[j4*4+2] = fmaf(qv, vv.z, o[j4*4+2]);
            o[j4*4+3] = fmaf(qv, vv.w, o[j4*4+3]);
        }
    }
    for (int s = 0; s <= t; ++s) {
        float av = GA[t][s];
        const float4* vp4 = (const float4*)&vs[s][qq*32];
#pragma unroll
        for (int j4 = 0; j4 < 8; ++j4) {
            float4 vv = vp4[j4];
            o[j4*4+0] = fmaf(av, vv.x, o[j4*4+0]);
            o[j4*4+1] = fmaf(av, vv.y, o[j4*4+1]);
            o[j4*4+2] = fmaf(av, vv.z, o[j4*4+2]);
            o[j4*4+3] = fmaf(av, vv.w, o[j4*4+3]);
        }
    }
    float s1 = 0.f;
#pragma unroll
    for (int jj = 0; jj < 32; ++jj) s1 += o[jj];
    s1 += __shfl_xor_sync(0xffffffffu, s1, 1);
    s1 += __shfl_xor_sync(0xffffffffu, s1, 2);
    float mean = s1 * (1.f/128.f);
    float s2 = 0.f;
#pragma unroll
    for (int jj = 0; jj < 32; ++jj) { float dv = o[jj] - mean; s2 = fmaf(dv, dv, s2); }
    s2 += __shfl_xor_sync(0xffffffffu, s2, 1);
    s2 += __shfl_xor_sync(0xffffffffu, s2, 2);
    float rstd = rsqrtf(s2 * (1.f/128.f) + LN_EPS);
    const int m = m0 + t;
    const float* gpp = g_gp + (size_t)m*D_ + h*DV + qq*32;
    float*       yp  = g_y  + (size_t)m*D_ + h*DV + qq*32;
#pragma unroll
    for (int jj = 0; jj < 32; ++jj) {
        float gv = gpp[jj];
        float si = gv / (1.f + __expf(-gv));
        yp[jj] = si * ((o[jj] - mean) * rstd);
    }
}

// ---------------- host driver -------------------------------------------------
extern "C" void kernel_launch(void* const* d_in, const int* in_sizes, int n_in,
                              void* d_out, int out_size)
{
    const float* x    = (const float*)d_in[0];
    const float* Wq   = (const float*)d_in[1];
    const float* Wk   = (const float*)d_in[2];
    const float* Wkg1 = (const float*)d_in[3];
    const float* Wkg2 = (const float*)d_in[4];
    const float* bkg2 = (const float*)d_in[5];
    const float* Wv   = (const float*)d_in[6];
    const float* Wg   = (const float*)d_in[7];
    const float* bg   = (const float*)d_in[8];
    const float* Wo   = (const float*)d_in[9];
    float* out = (float*)d_out;

    float *pq, *pk, *pv, *pgp, *pkg1, *py;
    cudaGetSymbolAddress((void**)&pq,   g_q);
    cudaGetSymbolAddress((void**)&pk,   g_k);
    cudaGetSymbolAddress((void**)&pv,   g_v);
    cudaGetSymbolAddress((void**)&pgp,  g_gp);
    cudaGetSymbolAddress((void**)&pkg1, g_kg1);
    cudaGetSymbolAddress((void**)&py,   g_y);

    cudaFuncSetAttribute(tf32_gemm_multi, cudaFuncAttributeMaxDynamicSharedMemorySize, GEMM_SMEM_BYTES);

    // merged projection GEMMs: tiles [0,8)=Wq, [8,16)=Wk, [16,32)=Wv, [32,48)=Wg
    tf32_gemm_multi<<<dim3(48, M_/BM), 256, GEMM_SMEM_BYTES>>>(
        x, Wq, Wk, Wv, Wg, bg,
        pq, pk, pv, pgp,
        D_,
        8, 16, 32,
        0, 0, 0,
        NQK, NQK, D_, D_,
        1.f, SCALE_QK, 1.f, 1.f);
    kg1_kernel<<<M_/16, 256>>>(x, Wkg1, pkg1);
    gate_kernel<<<M_, 256>>>(Wkg2, bkg2);

    // recurrence (chunked)
    const int smem8 = (2*64*68 + 64*65 + 2*64*132) * 4;
    cudaFuncSetAttribute(output_kernel, cudaFuncAttributeMaxDynamicSharedMemorySize, smem8);
    state_kernel<<<dim3(4, B_*H_), 128>>>();
    output_kernel<<<dim3(NCHUNK, B_*H_), 256, smem8>>>();

    // out = y @ Wo^T; tiles [8,16) read Wo rows 1024.. via pre-offset pointer
    tf32_gemm_multi<<<dim3(16, M_/BM), 256, GEMM_SMEM_BYTES>>>(
        py, Wo, Wo + (size_t)1024 * D_, Wo, Wo, nullptr,
        out, out, out, out,
        D_,
        8, 999, 999,
        1024, 0, 0,
        D_, D_, D_, D_,
        1.f, 1.f, 1.f, 1.f);
}

// round 8
// speedup vs baseline: 1.6321x; 1.6321x over previous
#include <cuda_runtime.h>
#include <cstdint>
#include <math.h>

// Problem dims (fixed)
#define B_      2
#define L_      2048
#define D_      2048
#define M_      4096          // B*L
#define H_      16
#define DK      64
#define DV      128
#define NQK     1024          // H*DK
#define CHUNK   64
#define NCHUNK  32            // L / CHUNK
#define SCALE_QK 0.08838834764831845f   // 128^-0.5
#define INV_NORM 0.0625f                 // 1/16
#define LN_EPS   1e-5f

// ---------------- scratch (static device globals; no allocation) -------------
__device__ float g_q   [(size_t)M_ * NQK];   // after prep: q * e^G
__device__ float g_k   [(size_t)M_ * NQK];   // after prep: k * e^-G (pre-scaled by SCALE_QK)
__device__ float g_gate[(size_t)M_ * NQK];
__device__ float g_kg1 [(size_t)M_ * 16];
__device__ float g_v   [(size_t)M_ * D_];
__device__ float g_gp  [(size_t)M_ * D_];
__device__ float g_y   [(size_t)M_ * D_];    // written tf32-rounded
__device__ float g_S   [(size_t)B_ * H_ * NCHUNK * DK * DV];
__device__ float g_E   [(size_t)B_ * H_ * NCHUNK * DK];      // per-chunk decay
__device__ float g_x   [(size_t)M_ * D_];    // tf32-rounded x
__device__ float g_w   [(size_t)8192 * D_];  // tf32-rounded Wq|Wk|Wv|Wg|Wo

#define WOFF_Q  0
#define WOFF_K  ((size_t)1024 * D_)
#define WOFF_V  ((size_t)2048 * D_)
#define WOFF_G  ((size_t)4096 * D_)
#define WOFF_O  ((size_t)6144 * D_)

// ======================= PTX helpers (non-'a' features only) ==================
__device__ __forceinline__ uint32_t smem_u32(const void* p) {
    uint32_t a;
    asm("{ .reg .u64 t; cvta.to.shared.u64 t, %1; cvt.u32.u64 %0, t; }" : "=r"(a) : "l"(p));
    return a;
}
__device__ __forceinline__ void cp_async16(uint32_t dst, const void* src) {
    asm volatile("cp.async.cg.shared.global [%0], [%1], 16;" :: "r"(dst), "l"(src) : "memory");
}
#define CP_COMMIT() asm volatile("cp.async.commit_group;" ::: "memory")
#define CP_WAIT(N)  asm volatile("cp.async.wait_group %0;" :: "n"(N) : "memory")

__device__ __forceinline__ uint32_t f2tf(float f) {
    uint32_t u;
    asm("cvt.rna.tf32.f32 %0, %1;" : "=r"(u) : "f"(f));
    return u;
}
__device__ __forceinline__ void mma_tf32(float c[4], const uint32_t a[4], const uint32_t b[2]) {
    asm volatile(
        "mma.sync.aligned.m16n8k8.row.col.f32.tf32.tf32.f32 "
        "{%0,%1,%2,%3}, {%4,%5,%6,%7}, {%8,%9}, {%0,%1,%2,%3};"
        : "+f"(c[0]), "+f"(c[1]), "+f"(c[2]), "+f"(c[3])
        : "r"(a[0]), "r"(a[1]), "r"(a[2]), "r"(a[3]), "r"(b[0]), "r"(b[1]));
}

// ---------------- tf32 rounding pass (elementwise) ----------------------------
__global__ __launch_bounds__(256) void rnd_kernel(const float4* __restrict__ src,
                                                  float4* __restrict__ dst, int n4)
{
    int i = blockIdx.x * blockDim.x + threadIdx.x;
    if (i < n4) {
        float4 v = src[i];
        float4 o;
        o.x = __uint_as_float(f2tf(v.x));
        o.y = __uint_as_float(f2tf(v.y));
        o.z = __uint_as_float(f2tf(v.z));
        o.w = __uint_as_float(f2tf(v.w));
        dst[i] = o;
    }
}

// ======================= tf32 GEMM (mma.sync), multi-target ===================
// A [M,K] row-major fp32 (ALREADY tf32-rounded). W selected by tile routing,
// rows tile-local: callers pre-offset W pointers for column ranges of one matrix.
// Tile 128x128x32, 8 warps (2x4), warp tile 64x32. cp.async double-buffered.
#define BM 128
#define BN 128
#define BK 32
#define PITCH 36
#define TSTRIDE (128*PITCH)
#define GEMM_SMEM_BYTES (4*TSTRIDE*4)

__global__ __launch_bounds__(256)
void tf32_gemm_multi(
    const float* __restrict__ A,
    const float* __restrict__ W0, const float* __restrict__ W1,
    const float* __restrict__ W2, const float* __restrict__ W3,
    const float* __restrict__ bias3,
    float* __restrict__ C0, float* __restrict__ C1,
    float* __restrict__ C2, float* __restrict__ C3,
    int K,
    int s1, int s2, int s3,
    int cb1, int cb2, int cb3,
    int N0, int N1, int N2, int N3,
    float a0, float a1, float a2, float a3)
{
    extern __shared__ float smf[];
    float* Asm = smf;
    float* Bsm = smf + 2*TSTRIDE;
    const uint32_t Abase_s = smem_u32(Asm);
    const uint32_t Bbase_s = smem_u32(Bsm);

    const int c = blockIdx.x;
    const int sel = (c >= s3) ? 3 : (c >= s2) ? 2 : (c >= s1) ? 1 : 0;
    const float* W = (sel == 0) ? W0 : (sel == 1) ? W1 : (sel == 2) ? W2 : W3;
    float*       C = (sel == 0) ? C0 : (sel == 1) ? C1 : (sel == 2) ? C2 : C3;
    const int start   = (sel == 0) ? 0 : (sel == 1) ? s1 : (sel == 2) ? s2 : s3;
    const int colbase = (sel == 0) ? 0 : (sel == 1) ? cb1 : (sel == 2) ? cb2 : cb3;
    const int N       = (sel == 0) ? N0 : (sel == 1) ? N1 : (sel == 2) ? N2 : N3;
    const float alpha = (sel == 0) ? a0 : (sel == 1) ? a1 : (sel == 2) ? a2 : a3;
    const float* bias = (sel == 3) ? bias3 : nullptr;

    const int tid = threadIdx.x;
    const int wid = tid >> 5;
    const int lane = tid & 31;
    const int g  = lane >> 2;
    const int t4 = lane & 3;
    const int wm = wid >> 2;
    const int wn = wid & 3;
    const int m0 = blockIdx.y * BM;
    const int wrow = (c - start) * BN;
    const int n0g = wrow + colbase;

    const float* Ag = A + (size_t)m0   * K;
    const float* Bg = W + (size_t)wrow * K;

    float cacc[4][4][4];
#pragma unroll
    for (int i = 0; i < 4; ++i)
#pragma unroll
        for (int j = 0; j < 4; ++j)
#pragma unroll
            for (int e = 0; e < 4; ++e) cacc[i][j][e] = 0.f;

    const int niter = K / BK;

    auto load_tile = [&](int kt, int s) {
        const int k0 = kt * BK;
        const uint32_t sa = Abase_s + (uint32_t)s * TSTRIDE * 4;
        const uint32_t sb = Bbase_s + (uint32_t)s * TSTRIDE * 4;
#pragma unroll
        for (int i = 0; i < 4; ++i) {
            int idx = tid + 256*i;
            int r = idx >> 3, sg = idx & 7;
            cp_async16(sa + (uint32_t)(r*PITCH + sg*4)*4, Ag + (size_t)r*K + k0 + sg*4);
        }
#pragma unroll
        for (int i = 0; i < 4; ++i) {
            int idx = tid + 256*i;
            int r = idx >> 3, sg = idx & 7;
            cp_async16(sb + (uint32_t)(r*PITCH + sg*4)*4, Bg + (size_t)r*K + k0 + sg*4);
        }
    };

    load_tile(0, 0);
    CP_COMMIT();

    for (int kt = 0; kt < niter; ++kt) {
        const int s = kt & 1;
        if (kt + 1 < niter) {
            load_tile(kt + 1, s ^ 1);
            CP_COMMIT();
            CP_WAIT(1);
        } else {
            CP_WAIT(0);
        }
        __syncthreads();

        const uint32_t* As = (const uint32_t*)(Asm + s * TSTRIDE);
        const uint32_t* Bs = (const uint32_t*)(Bsm + s * TSTRIDE);
#pragma unroll
        for (int kk = 0; kk < 4; ++kk) {
            uint32_t af[4][4];
#pragma unroll
            for (int mt = 0; mt < 4; ++mt) {
                const int r0 = wm*64 + mt*16 + g;
                const uint32_t* pa = As + kk*8 + t4;
                af[mt][0] = pa[(r0    )*PITCH    ];
                af[mt][1] = pa[(r0 + 8)*PITCH    ];
                af[mt][2] = pa[(r0    )*PITCH + 4];
                af[mt][3] = pa[(r0 + 8)*PITCH + 4];
            }
            uint32_t bf[4][2];
#pragma unroll
            for (int nt = 0; nt < 4; ++nt) {
                const int nr = wn*32 + nt*8 + g;
                const uint32_t* pb = Bs + (size_t)nr*PITCH + kk*8 + t4;
                bf[nt][0] = pb[0];
                bf[nt][1] = pb[4];
            }
#pragma unroll
            for (int mt = 0; mt < 4; ++mt)
#pragma unroll
                for (int nt = 0; nt < 4; ++nt)
                    mma_tf32(cacc[mt][nt], af[mt], bf[nt]);
        }
        __syncthreads();
    }

#pragma unroll
    for (int mt = 0; mt < 4; ++mt) {
#pragma unroll
        for (int nt = 0; nt < 4; ++nt) {
            const int col = n0g + wn*32 + nt*8 + 2*t4;
            float b0 = bias ? __ldg(bias + col)     : 0.f;
            float b1 = bias ? __ldg(bias + col + 1) : 0.f;
            const int r0 = m0 + wm*64 + mt*16 + g;
            float2 v0 = make_float2(cacc[mt][nt][0]*alpha + b0, cacc[mt][nt][1]*alpha + b1);
            float2 v1 = make_float2(cacc[mt][nt][2]*alpha + b0, cacc[mt][nt][3]*alpha + b1);
            *(float2*)(C + (size_t)r0      * N + col) = v0;
            *(float2*)(C + (size_t)(r0+8)  * N + col) = v1;
        }
    }
}

// ---------------- kg1 = x @ Wkg1^T  ------------------------------------------
__global__ __launch_bounds__(256) void kg1_kernel(
    const float* __restrict__ x, const float* __restrict__ Wkg1,
    float* __restrict__ out)
{
    __shared__ float xs[16][68];
    __shared__ float ws[16][68];
    const int tid = threadIdx.x;
    const int tx = tid & 15;
    const int ty = tid >> 4;
    const int m0 = blockIdx.x * 16;
    const int lrow = tid >> 4;
    const int lcol = (tid & 15) * 4;
    float acc = 0.f;
    for (int kt = 0; kt < D_; kt += 64) {
        float4 xv = *(const float4*)(x    + (size_t)(m0 + lrow)*D_ + kt + lcol);
        float4 wv = *(const float4*)(Wkg1 + (size_t)lrow*D_        + kt + lcol);
        *(float4*)&xs[lrow][lcol] = xv;
        *(float4*)&ws[lrow][lcol] = wv;
        __syncthreads();
#pragma unroll
        for (int kk = 0; kk < 64; ++kk)
            acc = fmaf(xs[ty][kk], ws[tx][kk], acc);
        __syncthreads();
    }
    out[(size_t)(m0 + ty)*16 + tx] = acc;
}

// ---------------- gate = log_sigmoid(kg1 @ Wkg2^T + bkg2) / 16 ---------------
__global__ __launch_bounds__(256) void gate_kernel(
    const float* __restrict__ Wkg2, const float* __restrict__ bkg2)
{
    __shared__ float row[16];
    const int tid = threadIdx.x;
    const int m = blockIdx.x;
    if (tid < 16) row[tid] = g_kg1[(size_t)m*16 + tid];
    __syncthreads();
#pragma unroll
    for (int i = 0; i < 4; ++i) {
        int n = i*256 + tid;
        const float4* wp = (const float4*)(Wkg2 + (size_t)n*16);
        float4 w0 = wp[0], w1 = wp[1], w2 = wp[2], w3 = wp[3];
        float acc = bkg2[n];
        acc += row[0]*w0.x + row[1]*w0.y + row[2]*w0.z + row[3]*w0.w;
        acc += row[4]*w1.x + row[5]*w1.y + row[6]*w1.z + row[7]*w1.w;
        acc += row[8]*w2.x + row[9]*w2.y + row[10]*w2.z + row[11]*w2.w;
        acc += row[12]*w3.x + row[13]*w3.y + row[14]*w3.z + row[15]*w3.w;
        float z = acc;
        float e  = __expf(-fabsf(z));
        float ls = fminf(z, 0.f) - __logf(1.f + e);
        g_gate[(size_t)m*NQK + n] = ls * INV_NORM;
    }
}

// ---------------- prep: cumsum gates, transform q/k in place, store E --------
// grid (NCHUNK, BH), 64 threads (one per dk lane)
__global__ __launch_bounds__(64) void prep_kernel()
{
    const int c  = blockIdx.x;
    const int bh = blockIdx.y;
    const int b = bh >> 4, h = bh & 15;
    const int d = threadIdx.x;
    const int m0 = b * L_ + c * CHUNK;
    size_t gi = (size_t)m0 * NQK + h * DK + d;
    float run = 0.f;
    for (int t = 0; t < CHUNK; ++t) {
        run += g_gate[gi];
        float eg = __expf(run);
        float en = __expf(-run);
        g_q[gi] *= eg;
        g_k[gi] *= en;
        gi += NQK;
    }
    g_E[(size_t)(bh * NCHUNK + c) * DK + d] = __expf(run);
}

// ---------------- pass 1: chunk states, cp.async pipelined -------------------
// grid (4 dv-quarters, 32 bh), 128 threads. S_new = E .* (S_prev + khat^T V)
#define SKP_K 68
#define SKP_V 36
#define STATE_SMEM ((2*64*SKP_K + 2*64*SKP_V)*4)

__global__ __launch_bounds__(128) void state_kernel()
{
    extern __shared__ float sms[];
    float* khs = sms;                    // [2][64][SKP_K]
    float* vvs = sms + 2*64*SKP_K;       // [2][64][SKP_V]
    const uint32_t kh_s = smem_u32(khs);
    const uint32_t vv_s = smem_u32(vvs);

    const int bq = blockIdx.x;
    const int bh = blockIdx.y;
    const int b = bh >> 4, h = bh & 15;
    const int tid = threadIdx.x;
    const int ty = tid >> 3;           // 0..15 (dk block of 4)
    const int tx = tid & 7;            // 0..7  (dv block of 4 within 32)
    const int mb = b * L_;

    auto prefetch = [&](int c, int s) {
        const int m0 = mb + c * CHUNK;
        const uint32_t ka = kh_s + (uint32_t)s * 64*SKP_K*4;
        const uint32_t va = vv_s + (uint32_t)s * 64*SKP_V*4;
#pragma unroll
        for (int i = 0; i < 8; ++i) {
            int e = tid + 128*i;          // 0..1023
            int t = e >> 4, q4 = (e & 15) * 4;
            cp_async16(ka + (uint32_t)(t*SKP_K + q4)*4,
                       g_k + (size_t)(m0 + t)*NQK + h*DK + q4);
        }
#pragma unroll
        for (int i = 0; i < 4; ++i) {
            int e = tid + 128*i;          // 0..511
            int t = e >> 3, q4 = (e & 7) * 4;
            cp_async16(va + (uint32_t)(t*SKP_V + q4)*4,
                       g_v + (size_t)(m0 + t)*D_ + h*DV + bq*32 + q4);
        }
    };

    float S[4][4];
#pragma unroll
    for (int dd = 0; dd < 4; ++dd)
#pragma unroll
        for (int jj = 0; jj < 4; ++jj) S[dd][jj] = 0.f;

    prefetch(0, 0);
    CP_COMMIT();

    for (int c = 0; c < NCHUNK; ++c) {
        const int s = c & 1;
        CP_WAIT(0);
        __syncthreads();
        if (c + 1 < NCHUNK) {
            prefetch(c + 1, s ^ 1);
            CP_COMMIT();
        }

        // store state BEFORE this chunk
        float* sp = g_S + (size_t)(bh * NCHUNK + c) * (DK * DV) + (size_t)bq * 32;
#pragma unroll
        for (int dd = 0; dd < 4; ++dd)
            *(float4*)(sp + (size_t)(ty*4 + dd)*DV + tx*4) =
                make_float4(S[dd][0], S[dd][1], S[dd][2], S[dd][3]);

        float acc[4][4];
#pragma unroll
        for (int dd = 0; dd < 4; ++dd)
#pragma unroll
            for (int jj = 0; jj < 4; ++jj) acc[dd][jj] = 0.f;

        const float* kb = khs + s * 64*SKP_K;
        const float* vb = vvs + s * 64*SKP_V;
        for (int t = 0; t < CHUNK; ++t) {
            float4 kv = *(const float4*)(kb + t*SKP_K + ty*4);
            float4 vv4 = *(const float4*)(vb + t*SKP_V + tx*4);
            float ka[4] = {kv.x, kv.y, kv.z, kv.w};
            float va[4] = {vv4.x, vv4.y, vv4.z, vv4.w};
#pragma unroll
            for (int dd = 0; dd < 4; ++dd)
#pragma unroll
                for (int jj = 0; jj < 4; ++jj)
                    acc[dd][jj] = fmaf(ka[dd], va[jj], acc[dd][jj]);
        }

        const float* ep = g_E + (size_t)(bh * NCHUNK + c) * DK + ty*4;
        float E[4] = {ep[0], ep[1], ep[2], ep[3]};
#pragma unroll
        for (int dd = 0; dd < 4; ++dd)
#pragma unroll
            for (int jj = 0; jj < 4; ++jj)
                S[dd][jj] = E[dd] * (S[dd][jj] + acc[dd][jj]);
    }
}

// ---------------- pass 2: chunk outputs + LN + SiLU gating --------------------
__global__ __launch_bounds__(256) void output_kernel()
{
    extern __shared__ float sm[];
    float (*qs)[68]  = (float(*)[68]) sm;
    float (*ks)[68]  = (float(*)[68])(sm + 64*68);
    float (*GA)[65]  = (float(*)[65])(sm + 2*64*68);
    float (*vs)[132] = (float(*)[132])(sm + 2*64*68 + 64*65);
    float (*Sp)[132] = (float(*)[132])(sm + 2*64*68 + 64*65 + 64*132);

    const int c  = blockIdx.x;
    const int bh = blockIdx.y;
    const int b = bh >> 4, h = bh & 15;
    const int tid = threadIdx.x;
    const int m0 = b * L_ + c * CHUNK;
    const size_t sbase = (size_t)(bh * NCHUNK + c) * (DK * DV);

    // q~ and k^ already transformed by prep_kernel
    for (int e = tid; e < CHUNK*DK; e += 256) {
        int t = e >> 6, d = e & 63;
        size_t gi = (size_t)(m0 + t)*NQK + h*DK + d;
        qs[t][d] = g_q[gi];
        ks[t][d] = g_k[gi];
    }
    for (int e = tid; e < CHUNK*DV; e += 256) {
        int t = e >> 7, j = e & 127;
        vs[t][j] = g_v[(size_t)(m0 + t)*D_ + h*DV + j];
        Sp[t][j] = g_S[sbase + e];
    }
    __syncthreads();
    for (int e = tid; e < CHUNK*CHUNK; e += 256) {
        int t = e >> 6, s = e & 63;
        float acc = 0.f;
        if (s <= t) {
            const float4* qp = (const float4*)&qs[t][0];
            const float4* kp = (const float4*)&ks[s][0];
#pragma unroll
            for (int d4 = 0; d4 < 16; ++d4) {
                float4 qa = qp[d4], kk4 = kp[d4];
                acc = fmaf(qa.x, kk4.x, acc);
                acc = fmaf(qa.y, kk4.y, acc);
                acc = fmaf(qa.z, kk4.z, acc);
                acc = fmaf(qa.w, kk4.w, acc);
            }
        }
        GA[t][s] = acc;
    }
    __syncthreads();
    const int t  = tid >> 2;
    const int qq = tid & 3;
    float o[32];
#pragma unroll
    for (int jj = 0; jj < 32; ++jj) o[jj] = 0.f;

    for (int d = 0; d < DK; ++d) {
        float qv = qs[t][d];
        const float4* sp4 = (const float4*)&Sp[d][qq*32];
#pragma unroll
        for (int j4 = 0; j4 < 8; ++j4) {
            float4 vv = sp4[j4];
            o[j4*4+0] = fmaf(qv, vv.x, o[j4*4+0]);
            o[j4*4+1] = fmaf(qv, vv.y, o[j4*4+1]);
            o[j4*4+2] = fmaf(qv, vv.z, o[j4*4+2]);
            o[j4*4+3] = fmaf(qv, vv.w, o[j4*4+3]);
        }
    }
    for (int s = 0; s <= t; ++s) {
        float av = GA[t][s];
        const float4* vp4 = (const float4*)&vs[s][qq*32];
#pragma unroll
        for (int j4 = 0; j4 < 8; ++j4) {
            float4 vv = vp4[j4];
            o[j4*4+0] = fmaf(av, vv.x, o[j4*4+0]);
            o[j4*4+1] = fmaf(av, vv.y, o[j4*4+1]);
            o[j4*4+2] = fmaf(av, vv.z, o[j4*4+2]);
            o[j4*4+3] = fmaf(av, vv.w, o[j4*4+3]);
        }
    }
    float s1 = 0.f;
#pragma unroll
    for (int jj = 0; jj < 32; ++jj) s1 += o[jj];
    s1 += __shfl_xor_sync(0xffffffffu, s1, 1);
    s1 += __shfl_xor_sync(0xffffffffu, s1, 2);
    float mean = s1 * (1.f/128.f);
    float s2 = 0.f;
#pragma unroll
    for (int jj = 0; jj < 32; ++jj) { float dv = o[jj] - mean; s2 = fmaf(dv, dv, s2); }
    s2 += __shfl_xor_sync(0xffffffffu, s2, 1);
    s2 += __shfl_xor_sync(0xffffffffu, s2, 2);
    float rstd = rsqrtf(s2 * (1.f/128.f) + LN_EPS);
    const int m = m0 + t;
    const float* gpp = g_gp + (size_t)m*D_ + h*DV + qq*32;
    float*       yp  = g_y  + (size_t)m*D_ + h*DV + qq*32;
#pragma unroll
    for (int jj = 0; jj < 32; ++jj) {
        float gv = gpp[jj];
        float si = gv / (1.f + __expf(-gv));
        // write y already tf32-rounded for the final tensor-core GEMM
        yp[jj] = __uint_as_float(f2tf(si * ((o[jj] - mean) * rstd)));
    }
}

// ---------------- host driver -------------------------------------------------
extern "C" void kernel_launch(void* const* d_in, const int* in_sizes, int n_in,
                              void* d_out, int out_size)
{
    const float* x    = (const float*)d_in[0];
    const float* Wq   = (const float*)d_in[1];
    const float* Wk   = (const float*)d_in[2];
    const float* Wkg1 = (const float*)d_in[3];
    const float* Wkg2 = (const float*)d_in[4];
    const float* bkg2 = (const float*)d_in[5];
    const float* Wv   = (const float*)d_in[6];
    const float* Wg   = (const float*)d_in[7];
    const float* bg   = (const float*)d_in[8];
    const float* Wo   = (const float*)d_in[9];
    float* out = (float*)d_out;

    float *pq, *pk, *pv, *pgp, *pkg1, *py, *px, *pw;
    cudaGetSymbolAddress((void**)&pq,   g_q);
    cudaGetSymbolAddress((void**)&pk,   g_k);
    cudaGetSymbolAddress((void**)&pv,   g_v);
    cudaGetSymbolAddress((void**)&pgp,  g_gp);
    cudaGetSymbolAddress((void**)&pkg1, g_kg1);
    cudaGetSymbolAddress((void**)&py,   g_y);
    cudaGetSymbolAddress((void**)&px,   g_x);
    cudaGetSymbolAddress((void**)&pw,   g_w);

    cudaFuncSetAttribute(tf32_gemm_multi, cudaFuncAttributeMaxDynamicSharedMemorySize, GEMM_SMEM_BYTES);
    cudaFuncSetAttribute(state_kernel,    cudaFuncAttributeMaxDynamicSharedMemorySize, STATE_SMEM);

    // tf32 rounding passes (A operands and all weights)
    {
        auto rnd = [&](const float* src, float* dst, size_t n) {
            int n4 = (int)(n / 4);
            rnd_kernel<<<(n4 + 255)/256, 256>>>((const float4*)src, (float4*)dst, n4);
        };
        rnd(x,  px,              (size_t)M_ * D_);
        rnd(Wq, pw + WOFF_Q,     (size_t)1024 * D_);
        rnd(Wk, pw + WOFF_K,     (size_t)1024 * D_);
        rnd(Wv, pw + WOFF_V,     (size_t)2048 * D_);
        rnd(Wg, pw + WOFF_G,     (size_t)2048 * D_);
        rnd(Wo, pw + WOFF_O,     (size_t)2048 * D_);
    }

    // merged projection GEMMs: tiles [0,8)=Wq, [8,16)=Wk, [16,32)=Wv, [32,48)=Wg
    tf32_gemm_multi<<<dim3(48, M_/BM), 256, GEMM_SMEM_BYTES>>>(
        px, pw + WOFF_Q, pw + WOFF_K, pw + WOFF_V, pw + WOFF_G, bg,
        pq, pk, pv, pgp,
        D_,
        8, 16, 32,
        0, 0, 0,
        NQK, NQK, D_, D_,
        1.f, SCALE_QK, 1.f, 1.f);
    kg1_kernel<<<M_/16, 256>>>(x, Wkg1, pkg1);
    gate_kernel<<<M_, 256>>>(Wkg2, bkg2);

    // gate cumsum + q/k transform (parallel), then recurrence
    prep_kernel<<<dim3(NCHUNK, B_*H_), 64>>>();
    state_kernel<<<dim3(4, B_*H_), 128, STATE_SMEM>>>();

    const int smem8 = (2*64*68 + 64*65 + 2*64*132) * 4;
    cudaFuncSetAttribute(output_kernel, cudaFuncAttributeMaxDynamicSharedMemorySize, smem8);
    output_kernel<<<dim3(NCHUNK, B_*H_), 256, smem8>>>();

    // out = y @ Wo^T; tiles [8,16) read Wo rows 1024.. via pre-offset pointer
    tf32_gemm_multi<<<dim3(16, M_/BM), 256, GEMM_SMEM_BYTES>>>(
        py, pw + WOFF_O, pw + WOFF_O + (size_t)1024 * D_, pw + WOFF_O, pw + WOFF_O, nullptr,
        out, out, out, out,
        D_,
        8, 999, 999,
        1024, 0, 0,
        D_, D_, D_, D_,
        1.f, 1.f, 1.f, 1.f);
}

// round 9
// speedup vs baseline: 1.7072x; 1.0460x over previous
#include <cuda_runtime.h>
#include <cstdint>
#include <math.h>

// Problem dims (fixed)
#define B_      2
#define L_      2048
#define D_      2048
#define M_      4096          // B*L
#define H_      16
#define DK      64
#define DV      128
#define NQK     1024          // H*DK
#define CHUNK   64
#define NCHUNK  32            // L / CHUNK
#define SCALE_QK 0.08838834764831845f   // 128^-0.5
#define INV_NORM 0.0625f                 // 1/16
#define LN_EPS   1e-5f

// ---------------- scratch (static device globals; no allocation) -------------
__device__ float g_q   [(size_t)M_ * NQK];   // after prep: q * e^G
__device__ float g_k   [(size_t)M_ * NQK];   // after prep: k * e^-G (pre-scaled by SCALE_QK)
__device__ float g_gate[(size_t)M_ * NQK];
__device__ float g_kg1 [(size_t)M_ * 16];
__device__ float g_v   [(size_t)M_ * D_];
__device__ float g_gp  [(size_t)M_ * D_];
__device__ float g_y   [(size_t)M_ * D_];    // written tf32-rounded
__device__ float g_S   [(size_t)B_ * H_ * NCHUNK * DK * DV];
__device__ float g_E   [(size_t)B_ * H_ * NCHUNK * DK];      // per-chunk decay
__device__ float g_x   [(size_t)M_ * D_];    // tf32-rounded x
__device__ float g_w   [(size_t)8192 * D_];  // tf32-rounded Wq|Wk|Wv|Wg|Wo

#define WOFF_Q  0
#define WOFF_K  ((size_t)1024 * D_)
#define WOFF_V  ((size_t)2048 * D_)
#define WOFF_G  ((size_t)4096 * D_)
#define WOFF_O  ((size_t)6144 * D_)

// ======================= PTX helpers (non-'a' features only) ==================
__device__ __forceinline__ uint32_t smem_u32(const void* p) {
    uint32_t a;
    asm("{ .reg .u64 t; cvta.to.shared.u64 t, %1; cvt.u32.u64 %0, t; }" : "=r"(a) : "l"(p));
    return a;
}
__device__ __forceinline__ void cp_async16(uint32_t dst, const void* src) {
    asm volatile("cp.async.cg.shared.global [%0], [%1], 16;" :: "r"(dst), "l"(src) : "memory");
}
#define CP_COMMIT() asm volatile("cp.async.commit_group;" ::: "memory")
#define CP_WAIT(N)  asm volatile("cp.async.wait_group %0;" :: "n"(N) : "memory")

__device__ __forceinline__ uint32_t f2tf(float f) {
    uint32_t u;
    asm("cvt.rna.tf32.f32 %0, %1;" : "=r"(u) : "f"(f));
    return u;
}
__device__ __forceinline__ void mma_tf32(float c[4], const uint32_t a[4], const uint32_t b[2]) {
    asm volatile(
        "mma.sync.aligned.m16n8k8.row.col.f32.tf32.tf32.f32 "
        "{%0,%1,%2,%3}, {%4,%5,%6,%7}, {%8,%9}, {%0,%1,%2,%3};"
        : "+f"(c[0]), "+f"(c[1]), "+f"(c[2]), "+f"(c[3])
        : "r"(a[0]), "r"(a[1]), "r"(a[2]), "r"(a[3]), "r"(b[0]), "r"(b[1]));
}

// ---------------- fused tf32 rounding pass (segmented) ------------------------
// blockIdx.y selects segment; one launch rounds x and all 5 weight matrices.
__global__ __launch_bounds__(256) void rnd_all_kernel(
    const float4* __restrict__ x,
    const float4* __restrict__ Wq, const float4* __restrict__ Wk,
    const float4* __restrict__ Wv, const float4* __restrict__ Wg,
    const float4* __restrict__ Wo,
    float4* __restrict__ dx, float4* __restrict__ dw)
{
    const int seg = blockIdx.y;
    const float4* src;
    float4* dst;
    int n4;
    switch (seg) {
        case 0: src = x;  dst = dx;                  n4 = M_*D_/4;     break;
        case 1: src = Wq; dst = dw + WOFF_Q/4;       n4 = 1024*D_/4;   break;
        case 2: src = Wk; dst = dw + WOFF_K/4;       n4 = 1024*D_/4;   break;
        case 3: src = Wv; dst = dw + WOFF_V/4;       n4 = 2048*D_/4;   break;
        case 4: src = Wg; dst = dw + WOFF_G/4;       n4 = 2048*D_/4;   break;
        default:src = Wo; dst = dw + WOFF_O/4;       n4 = 2048*D_/4;   break;
    }
    int i = blockIdx.x * blockDim.x + threadIdx.x;
    if (i < n4) {
        float4 v = src[i];
        float4 o;
        o.x = __uint_as_float(f2tf(v.x));
        o.y = __uint_as_float(f2tf(v.y));
        o.z = __uint_as_float(f2tf(v.z));
        o.w = __uint_as_float(f2tf(v.w));
        dst[i] = o;
    }
}

// ======================= tf32 GEMM (mma.sync), multi-target ===================
// A [M,K] row-major fp32 (ALREADY tf32-rounded). W selected by tile routing,
// rows tile-local: callers pre-offset W pointers for column ranges of one matrix.
// Tile 128x128x32, 8 warps (2x4), warp tile 64x32. cp.async double-buffered.
#define BM 128
#define BN 128
#define BK 32
#define PITCH 36
#define TSTRIDE (128*PITCH)
#define GEMM_SMEM_BYTES (4*TSTRIDE*4)

__global__ __launch_bounds__(256, 2)
void tf32_gemm_multi(
    const float* __restrict__ A,
    const float* __restrict__ W0, const float* __restrict__ W1,
    const float* __restrict__ W2, const float* __restrict__ W3,
    const float* __restrict__ bias3,
    float* __restrict__ C0, float* __restrict__ C1,
    float* __restrict__ C2, float* __restrict__ C3,
    int K,
    int s1, int s2, int s3,
    int cb1, int cb2, int cb3,
    int N0, int N1, int N2, int N3,
    float a0, float a1, float a2, float a3)
{
    extern __shared__ float smf[];
    float* Asm = smf;
    float* Bsm = smf + 2*TSTRIDE;
    const uint32_t Abase_s = smem_u32(Asm);
    const uint32_t Bbase_s = smem_u32(Bsm);

    const int c = blockIdx.x;
    const int sel = (c >= s3) ? 3 : (c >= s2) ? 2 : (c >= s1) ? 1 : 0;
    const float* W = (sel == 0) ? W0 : (sel == 1) ? W1 : (sel == 2) ? W2 : W3;
    float*       C = (sel == 0) ? C0 : (sel == 1) ? C1 : (sel == 2) ? C2 : C3;
    const int start   = (sel == 0) ? 0 : (sel == 1) ? s1 : (sel == 2) ? s2 : s3;
    const int colbase = (sel == 0) ? 0 : (sel == 1) ? cb1 : (sel == 2) ? cb2 : cb3;
    const int N       = (sel == 0) ? N0 : (sel == 1) ? N1 : (sel == 2) ? N2 : N3;
    const float alpha = (sel == 0) ? a0 : (sel == 1) ? a1 : (sel == 2) ? a2 : a3;
    const float* bias = (sel == 3) ? bias3 : nullptr;

    const int tid = threadIdx.x;
    const int wid = tid >> 5;
    const int lane = tid & 31;
    const int g  = lane >> 2;
    const int t4 = lane & 3;
    const int wm = wid >> 2;
    const int wn = wid & 3;
    const int m0 = blockIdx.y * BM;
    const int wrow = (c - start) * BN;
    const int n0g = wrow + colbase;

    const float* Ag = A + (size_t)m0   * K;
    const float* Bg = W + (size_t)wrow * K;

    float cacc[4][4][4];
#pragma unroll
    for (int i = 0; i < 4; ++i)
#pragma unroll
        for (int j = 0; j < 4; ++j)
#pragma unroll
            for (int e = 0; e < 4; ++e) cacc[i][j][e] = 0.f;

    const int niter = K / BK;

    auto load_tile = [&](int kt, int s) {
        const int k0 = kt * BK;
        const uint32_t sa = Abase_s + (uint32_t)s * TSTRIDE * 4;
        const uint32_t sb = Bbase_s + (uint32_t)s * TSTRIDE * 4;
#pragma unroll
        for (int i = 0; i < 4; ++i) {
            int idx = tid + 256*i;
            int r = idx >> 3, sg = idx & 7;
            cp_async16(sa + (uint32_t)(r*PITCH + sg*4)*4, Ag + (size_t)r*K + k0 + sg*4);
        }
#pragma unroll
        for (int i = 0; i < 4; ++i) {
            int idx = tid + 256*i;
            int r = idx >> 3, sg = idx & 7;
            cp_async16(sb + (uint32_t)(r*PITCH + sg*4)*4, Bg + (size_t)r*K + k0 + sg*4);
        }
    };

    load_tile(0, 0);
    CP_COMMIT();

    for (int kt = 0; kt < niter; ++kt) {
        const int s = kt & 1;
        if (kt + 1 < niter) {
            load_tile(kt + 1, s ^ 1);
            CP_COMMIT();
            CP_WAIT(1);
        } else {
            CP_WAIT(0);
        }
        __syncthreads();

        const uint32_t* As = (const uint32_t*)(Asm + s * TSTRIDE);
        const uint32_t* Bs = (const uint32_t*)(Bsm + s * TSTRIDE);
#pragma unroll
        for (int kk = 0; kk < 4; ++kk) {
            uint32_t af[4][4];
#pragma unroll
            for (int mt = 0; mt < 4; ++mt) {
                const int r0 = wm*64 + mt*16 + g;
                const uint32_t* pa = As + kk*8 + t4;
                af[mt][0] = pa[(r0    )*PITCH    ];
                af[mt][1] = pa[(r0 + 8)*PITCH    ];
                af[mt][2] = pa[(r0    )*PITCH + 4];
                af[mt][3] = pa[(r0 + 8)*PITCH + 4];
            }
            uint32_t bf[4][2];
#pragma unroll
            for (int nt = 0; nt < 4; ++nt) {
                const int nr = wn*32 + nt*8 + g;
                const uint32_t* pb = Bs + (size_t)nr*PITCH + kk*8 + t4;
                bf[nt][0] = pb[0];
                bf[nt][1] = pb[4];
            }
#pragma unroll
            for (int mt = 0; mt < 4; ++mt)
#pragma unroll
                for (int nt = 0; nt < 4; ++nt)
                    mma_tf32(cacc[mt][nt], af[mt], bf[nt]);
        }
        __syncthreads();
    }

#pragma unroll
    for (int mt = 0; mt < 4; ++mt) {
#pragma unroll
        for (int nt = 0; nt < 4; ++nt) {
            const int col = n0g + wn*32 + nt*8 + 2*t4;
            float b0 = bias ? __ldg(bias + col)     : 0.f;
            float b1 = bias ? __ldg(bias + col + 1) : 0.f;
            const int r0 = m0 + wm*64 + mt*16 + g;
            float2 v0 = make_float2(cacc[mt][nt][0]*alpha + b0, cacc[mt][nt][1]*alpha + b1);
            float2 v1 = make_float2(cacc[mt][nt][2]*alpha + b0, cacc[mt][nt][3]*alpha + b1);
            *(float2*)(C + (size_t)r0      * N + col) = v0;
            *(float2*)(C + (size_t)(r0+8)  * N + col) = v1;
        }
    }
}

// ---------------- kg1 = x @ Wkg1^T  ------------------------------------------
__global__ __launch_bounds__(256) void kg1_kernel(
    const float* __restrict__ x, const float* __restrict__ Wkg1,
    float* __restrict__ out)
{
    __shared__ float xs[16][68];
    __shared__ float ws[16][68];
    const int tid = threadIdx.x;
    const int tx = tid & 15;
    const int ty = tid >> 4;
    const int m0 = blockIdx.x * 16;
    const int lrow = tid >> 4;
    const int lcol = (tid & 15) * 4;
    float acc = 0.f;
    for (int kt = 0; kt < D_; kt += 64) {
        float4 xv = *(const float4*)(x    + (size_t)(m0 + lrow)*D_ + kt + lcol);
        float4 wv = *(const float4*)(Wkg1 + (size_t)lrow*D_        + kt + lcol);
        *(float4*)&xs[lrow][lcol] = xv;
        *(float4*)&ws[lrow][lcol] = wv;
        __syncthreads();
#pragma unroll
        for (int kk = 0; kk < 64; ++kk)
            acc = fmaf(xs[ty][kk], ws[tx][kk], acc);
        __syncthreads();
    }
    out[(size_t)(m0 + ty)*16 + tx] = acc;
}

// ---------------- gate = log_sigmoid(kg1 @ Wkg2^T + bkg2) / 16 ---------------
__global__ __launch_bounds__(256) void gate_kernel(
    const float* __restrict__ Wkg2, const float* __restrict__ bkg2)
{
    __shared__ float row[16];
    const int tid = threadIdx.x;
    const int m = blockIdx.x;
    if (tid < 16) row[tid] = g_kg1[(size_t)m*16 + tid];
    __syncthreads();
#pragma unroll
    for (int i = 0; i < 4; ++i) {
        int n = i*256 + tid;
        const float4* wp = (const float4*)(Wkg2 + (size_t)n*16);
        float4 w0 = wp[0], w1 = wp[1], w2 = wp[2], w3 = wp[3];
        float acc = bkg2[n];
        acc += row[0]*w0.x + row[1]*w0.y + row[2]*w0.z + row[3]*w0.w;
        acc += row[4]*w1.x + row[5]*w1.y + row[6]*w1.z + row[7]*w1.w;
        acc += row[8]*w2.x + row[9]*w2.y + row[10]*w2.z + row[11]*w2.w;
        acc += row[12]*w3.x + row[13]*w3.y + row[14]*w3.z + row[15]*w3.w;
        float z = acc;
        float e  = __expf(-fabsf(z));
        float ls = fminf(z, 0.f) - __logf(1.f + e);
        g_gate[(size_t)m*NQK + n] = ls * INV_NORM;
    }
}

// ---------------- prep: cumsum gates, transform q/k in place, store E --------
__global__ __launch_bounds__(64) void prep_kernel()
{
    const int c  = blockIdx.x;
    const int bh = blockIdx.y;
    const int b = bh >> 4, h = bh & 15;
    const int d = threadIdx.x;
    const int m0 = b * L_ + c * CHUNK;
    size_t gi = (size_t)m0 * NQK + h * DK + d;
    float run = 0.f;
    for (int t = 0; t < CHUNK; ++t) {
        run += g_gate[gi];
        float eg = __expf(run);
        float en = __expf(-run);
        g_q[gi] *= eg;
        g_k[gi] *= en;
        gi += NQK;
    }
    g_E[(size_t)(bh * NCHUNK + c) * DK + d] = __expf(run);
}

// ---------------- pass 1: chunk states, cp.async pipelined -------------------
#define SKP_K 68
#define SKP_V 36
#define STATE_SMEM ((2*64*SKP_K + 2*64*SKP_V)*4)

__global__ __launch_bounds__(128) void state_kernel()
{
    extern __shared__ float sms[];
    float* khs = sms;                    // [2][64][SKP_K]
    float* vvs = sms + 2*64*SKP_K;       // [2][64][SKP_V]
    const uint32_t kh_s = smem_u32(khs);
    const uint32_t vv_s = smem_u32(vvs);

    const int bq = blockIdx.x;
    const int bh = blockIdx.y;
    const int b = bh >> 4, h = bh & 15;
    const int tid = threadIdx.x;
    const int ty = tid >> 3;
    const int tx = tid & 7;
    const int mb = b * L_;

    auto prefetch = [&](int c, int s) {
        const int m0 = mb + c * CHUNK;
        const uint32_t ka = kh_s + (uint32_t)s * 64*SKP_K*4;
        const uint32_t va = vv_s + (uint32_t)s * 64*SKP_V*4;
#pragma unroll
        for (int i = 0; i < 8; ++i) {
            int e = tid + 128*i;
            int t = e >> 4, q4 = (e & 15) * 4;
            cp_async16(ka + (uint32_t)(t*SKP_K + q4)*4,
                       g_k + (size_t)(m0 + t)*NQK + h*DK + q4);
        }
#pragma unroll
        for (int i = 0; i < 4; ++i) {
            int e = tid + 128*i;
            int t = e >> 3, q4 = (e & 7) * 4;
            cp_async16(va + (uint32_t)(t*SKP_V + q4)*4,
                       g_v + (size_t)(m0 + t)*D_ + h*DV + bq*32 + q4);
        }
    };

    float S[4][4];
#pragma unroll
    for (int dd = 0; dd < 4; ++dd)
#pragma unroll
        for (int jj = 0; jj < 4; ++jj) S[dd][jj] = 0.f;

    prefetch(0, 0);
    CP_COMMIT();

    for (int c = 0; c < NCHUNK; ++c) {
        const int s = c & 1;
        CP_WAIT(0);
        __syncthreads();
        if (c + 1 < NCHUNK) {
            prefetch(c + 1, s ^ 1);
            CP_COMMIT();
        }

        float* sp = g_S + (size_t)(bh * NCHUNK + c) * (DK * DV) + (size_t)bq * 32;
#pragma unroll
        for (int dd = 0; dd < 4; ++dd)
            *(float4*)(sp + (size_t)(ty*4 + dd)*DV + tx*4) =
                make_float4(S[dd][0], S[dd][1], S[dd][2], S[dd][3]);

        float acc[4][4];
#pragma unroll
        for (int dd = 0; dd < 4; ++dd)
#pragma unroll
            for (int jj = 0; jj < 4; ++jj) acc[dd][jj] = 0.f;

        const float* kb = khs + s * 64*SKP_K;
        const float* vb = vvs + s * 64*SKP_V;
        for (int t = 0; t < CHUNK; ++t) {
            float4 kv = *(const float4*)(kb + t*SKP_K + ty*4);
            float4 vv4 = *(const float4*)(vb + t*SKP_V + tx*4);
            float ka[4] = {kv.x, kv.y, kv.z, kv.w};
            float va[4] = {vv4.x, vv4.y, vv4.z, vv4.w};
#pragma unroll
            for (int dd = 0; dd < 4; ++dd)
#pragma unroll
                for (int jj = 0; jj < 4; ++jj)
                    acc[dd][jj] = fmaf(ka[dd], va[jj], acc[dd][jj]);
        }

        const float* ep = g_E + (size_t)(bh * NCHUNK + c) * DK + ty*4;
        float E[4] = {ep[0], ep[1], ep[2], ep[3]};
#pragma unroll
        for (int dd = 0; dd < 4; ++dd)
#pragma unroll
            for (int jj = 0; jj < 4; ++jj)
                S[dd][jj] = E[dd] * (S[dd][jj] + acc[dd][jj]);
    }
}

// ---------------- pass 2: chunk outputs + LN + SiLU gating --------------------
// smem reduced: one [64][132] buffer reused for S_prev then V (85KB -> 2 CTA/SM)
#define OUT_SMEM ((2*64*68 + 64*65 + 64*132)*4)

__global__ __launch_bounds__(256) void output_kernel()
{
    extern __shared__ float sm[];
    float (*qs)[68]  = (float(*)[68]) sm;
    float (*ks)[68]  = (float(*)[68])(sm + 64*68);
    float (*GA)[65]  = (float(*)[65])(sm + 2*64*68);
    float (*buf)[132]= (float(*)[132])(sm + 2*64*68 + 64*65);   // Sp, then V

    const int c  = blockIdx.x;
    const int bh = blockIdx.y;
    const int b = bh >> 4, h = bh & 15;
    const int tid = threadIdx.x;
    const int m0 = b * L_ + c * CHUNK;
    const size_t sbase = (size_t)(bh * NCHUNK + c) * (DK * DV);

    // load q~, k^ and S_prev
    for (int e = tid; e < CHUNK*DK; e += 256) {
        int t = e >> 6, d = e & 63;
        size_t gi = (size_t)(m0 + t)*NQK + h*DK + d;
        qs[t][d] = g_q[gi];
        ks[t][d] = g_k[gi];
    }
    for (int e = tid; e < DK*DV; e += 256) {
        int t = e >> 7, j = e & 127;
        buf[t][j] = g_S[sbase + e];
    }
    __syncthreads();

    // A[t][s] = (s<=t) ? q~_t . k^_s : 0
    for (int e = tid; e < CHUNK*CHUNK; e += 256) {
        int t = e >> 6, s = e & 63;
        float acc = 0.f;
        if (s <= t) {
            const float4* qp = (const float4*)&qs[t][0];
            const float4* kp = (const float4*)&ks[s][0];
#pragma unroll
            for (int d4 = 0; d4 < 16; ++d4) {
                float4 qa = qp[d4], kk4 = kp[d4];
                acc = fmaf(qa.x, kk4.x, acc);
                acc = fmaf(qa.y, kk4.y, acc);
                acc = fmaf(qa.z, kk4.z, acc);
                acc = fmaf(qa.w, kk4.w, acc);
            }
        }
        GA[t][s] = acc;
    }

    const int t  = tid >> 2;
    const int qq = tid & 3;
    float o[32];
#pragma unroll
    for (int jj = 0; jj < 32; ++jj) o[jj] = 0.f;

    // phase 1: o += q~_t @ S_prev (buf holds Sp)
    for (int d = 0; d < DK; ++d) {
        float qv = qs[t][d];
        const float4* sp4 = (const float4*)&buf[d][qq*32];
#pragma unroll
        for (int j4 = 0; j4 < 8; ++j4) {
            float4 vv = sp4[j4];
            o[j4*4+0] = fmaf(qv, vv.x, o[j4*4+0]);
            o[j4*4+1] = fmaf(qv, vv.y, o[j4*4+1]);
            o[j4*4+2] = fmaf(qv, vv.z, o[j4*4+2]);
            o[j4*4+3] = fmaf(qv, vv.w, o[j4*4+3]);
        }
    }
    __syncthreads();
    // reload buf with V
    for (int e = tid; e < CHUNK*DV; e += 256) {
        int s = e >> 7, j = e & 127;
        buf[s][j] = g_v[(size_t)(m0 + s)*D_ + h*DV + j];
    }
    __syncthreads();
    // phase 2: o += A[t,:] @ V
    for (int s = 0; s <= t; ++s) {
        float av = GA[t][s];
        const float4* vp4 = (const float4*)&buf[s][qq*32];
#pragma unroll
        for (int j4 = 0; j4 < 8; ++j4) {
            float4 vv = vp4[j4];
            o[j4*4+0] = fmaf(av, vv.x, o[j4*4+0]);
            o[j4*4+1] = fmaf(av, vv.y, o[j4*4+1]);
            o[j4*4+2] = fmaf(av, vv.z, o[j4*4+2]);
            o[j4*4+3] = fmaf(av, vv.w, o[j4*4+3]);
        }
    }

    // LayerNorm over 128-wide head row (4 threads/row)
    float s1 = 0.f;
#pragma unroll
    for (int jj = 0; jj < 32; ++jj) s1 += o[jj];
    s1 += __shfl_xor_sync(0xffffffffu, s1, 1);
    s1 += __shfl_xor_sync(0xffffffffu, s1, 2);
    float mean = s1 * (1.f/128.f);
    float s2 = 0.f;
#pragma unroll
    for (int jj = 0; jj < 32; ++jj) { float dv = o[jj] - mean; s2 = fmaf(dv, dv, s2); }
    s2 += __shfl_xor_sync(0xffffffffu, s2, 1);
    s2 += __shfl_xor_sync(0xffffffffu, s2, 2);
    float rstd = rsqrtf(s2 * (1.f/128.f) + LN_EPS);
    const int m = m0 + t;
    const float* gpp = g_gp + (size_t)m*D_ + h*DV + qq*32;
    float*       yp  = g_y  + (size_t)m*D_ + h*DV + qq*32;
#pragma unroll
    for (int jj = 0; jj < 32; ++jj) {
        float gv = gpp[jj];
        float si = gv / (1.f + __expf(-gv));
        yp[jj] = __uint_as_float(f2tf(si * ((o[jj] - mean) * rstd)));
    }
}

// ---------------- host driver -------------------------------------------------
extern "C" void kernel_launch(void* const* d_in, const int* in_sizes, int n_in,
                              void* d_out, int out_size)
{
    const float* x    = (const float*)d_in[0];
    const float* Wq   = (const float*)d_in[1];
    const float* Wk   = (const float*)d_in[2];
    const float* Wkg1 = (const float*)d_in[3];
    const float* Wkg2 = (const float*)d_in[4];
    const float* bkg2 = (const float*)d_in[5];
    const float* Wv   = (const float*)d_in[6];
    const float* Wg   = (const float*)d_in[7];
    const float* bg   = (const float*)d_in[8];
    const float* Wo   = (const float*)d_in[9];
    float* out = (float*)d_out;

    float *pq, *pk, *pv, *pgp, *pkg1, *py, *px, *pw;
    cudaGetSymbolAddress((void**)&pq,   g_q);
    cudaGetSymbolAddress((void**)&pk,   g_k);
    cudaGetSymbolAddress((void**)&pv,   g_v);
    cudaGetSymbolAddress((void**)&pgp,  g_gp);
    cudaGetSymbolAddress((void**)&pkg1, g_kg1);
    cudaGetSymbolAddress((void**)&py,   g_y);
    cudaGetSymbolAddress((void**)&px,   g_x);
    cudaGetSymbolAddress((void**)&pw,   g_w);

    cudaFuncSetAttribute(tf32_gemm_multi, cudaFuncAttributeMaxDynamicSharedMemorySize, GEMM_SMEM_BYTES);
    cudaFuncSetAttribute(state_kernel,    cudaFuncAttributeMaxDynamicSharedMemorySize, STATE_SMEM);
    cudaFuncSetAttribute(output_kernel,   cudaFuncAttributeMaxDynamicSharedMemorySize, OUT_SMEM);

    // single fused tf32 rounding launch (x + all weights)
    rnd_all_kernel<<<dim3((M_*D_/4 + 255)/256, 6), 256>>>(
        (const float4*)x, (const float4*)Wq, (const float4*)Wk,
        (const float4*)Wv, (const float4*)Wg, (const float4*)Wo,
        (float4*)px, (float4*)pw);

    // merged projection GEMMs: tiles [0,8)=Wq, [8,16)=Wk, [16,32)=Wv, [32,48)=Wg
    tf32_gemm_multi<<<dim3(48, M_/BM), 256, GEMM_SMEM_BYTES>>>(
        px, pw + WOFF_Q, pw + WOFF_K, pw + WOFF_V, pw + WOFF_G, bg,
        pq, pk, pv, pgp,
        D_,
        8, 16, 32,
        0, 0, 0,
        NQK, NQK, D_, D_,
        1.f, SCALE_QK, 1.f, 1.f);
    kg1_kernel<<<M_/16, 256>>>(x, Wkg1, pkg1);
    gate_kernel<<<M_, 256>>>(Wkg2, bkg2);

    // gate cumsum + q/k transform (parallel), then recurrence
    prep_kernel<<<dim3(NCHUNK, B_*H_), 64>>>();
    state_kernel<<<dim3(4, B_*H_), 128, STATE_SMEM>>>();
    output_kernel<<<dim3(NCHUNK, B_*H_), 256, OUT_SMEM>>>();

    // out = y @ Wo^T; tiles [8,16) read Wo rows 1024.. via pre-offset pointer
    tf32_gemm_multi<<<dim3(16, M_/BM), 256, GEMM_SMEM_BYTES>>>(
        py, pw + WOFF_O, pw + WOFF_O + (size_t)1024 * D_, pw + WOFF_O, pw + WOFF_O, nullptr,
        out, out, out, out,
        D_,
        8, 999, 999,
        1024, 0, 0,
        D_, D_, D_, D_,
        1.f, 1.f, 1.f, 1.f);
}